// round 16
// baseline (speedup 1.0000x reference)
#include <cuda_runtime.h>
#include <cstdint>

#define NPTS 12288
#define DW   384           // 32-bit words per adjacency row (12288/32)
#define DC   (DW / 4)      // 96 uint4 chunks per row
#define EPS2 0.25f
#define MIN_SAMPLES 5
#define JT   256           // square tile side in k_adj
#define NTILE 48           // NPTS / JT
#define NTRI  (NTILE * (NTILE + 1) / 2)   // 1176 upper-tri tiles

#define CC_GRID   148
#define CC_WARPS  (CC_GRID * 32)          // 4736 global warps

typedef unsigned long long ull;

// ---------------- device scratch (no dynamic allocation allowed) -------------
__device__ __align__(16) unsigned g_adj[NPTS * DW];    // 18.9 MB adjacency bitmap
__device__ __align__(16) int g_partial[NPTS * NTILE];  // per-(row,tile) popc; every
                                                       // slot written each run
__device__ int      g_parent[NPTS];     // union-find parents
__device__ int      g_core[NPTS];       // core mask
__device__ __align__(16) unsigned g_corebits[DW];      // core mask, bit-packed
__device__ int      g_lbl[NPTS];        // final root per core (NPTS else)
__device__ int      g_root[NPTS];       // border root (non-core rows)
__device__ int      g_rank[NPTS];       // cumsum(is_root)-1

// software grid barrier state (generation-based; survives graph replays)
__device__ volatile int g_bar_gen;
__device__ int          g_bar_count;

// ---------------- f32x2 packed-math helpers (sm_100+) ------------------------
__device__ __forceinline__ ull pack2(float lo, float hi) {
    ull r;
    asm("mov.b64 %0, {%1, %2};" : "=l"(r) : "f"(lo), "f"(hi));
    return r;
}
__device__ __forceinline__ ull mul2(ull a, ull b) {
    ull d;
    asm("mul.rn.f32x2 %0, %1, %2;" : "=l"(d) : "l"(a), "l"(b));
    return d;
}
__device__ __forceinline__ ull fma2(ull a, ull b, ull c) {
    ull d;
    asm("fma.rn.f32x2 %0, %1, %2, %3;" : "=l"(d) : "l"(a), "l"(b), "l"(c));
    return d;
}
__device__ __forceinline__ ull add2(ull a, ull b) {
    ull d;
    asm("add.rn.f32x2 %0, %1, %2;" : "=l"(d) : "l"(a), "l"(b));
    return d;
}
__device__ __forceinline__ void unpack2(ull v, float& lo, float& hi) {
    asm("mov.b64 {%0, %1}, %2;" : "=f"(lo), "=f"(hi) : "l"(v));
}

__device__ __forceinline__ float norm8(float4 a, float4 b) {
    float s = a.x * a.x;
    s = fmaf(a.y, a.y, s);
    s = fmaf(a.z, a.z, s);
    s = fmaf(a.w, a.w, s);
    s = fmaf(b.x, b.x, s);
    s = fmaf(b.y, b.y, s);
    s = fmaf(b.z, b.z, s);
    s = fmaf(b.w, b.w, s);
    return s;
}

// 32x32 bit-matrix transpose within a warp (5 block-swap stages).
__device__ __forceinline__ unsigned bit_transpose32(unsigned x, int lane) {
    const unsigned masks[5] = {0xAAAAAAAAu, 0xCCCCCCCCu, 0xF0F0F0F0u,
                               0xFF00FF00u, 0xFFFF0000u};
#pragma unroll
    for (int si = 0; si < 5; si++) {
        int s = 1 << si;
        unsigned m = masks[si];
        unsigned y = __shfl_xor_sync(0xffffffffu, x, s);
        if (lane & s)
            x = (x & m) | ((y & m) >> s);
        else
            x = (x & ~m) | ((y & ~m) << s);
    }
    return x;
}

// ---------------- K1: adjacency bitmap + per-tile density partials -----------
__global__ void __launch_bounds__(256) k_adj(const float* __restrict__ X) {
    // decode linear tile id -> (by, bx) with bx >= by (row-major upper tri)
    int tid_lin = blockIdx.x;
    float ff = __int2float_rn(tid_lin);
    int by = __float2int_rd((2.0f * NTILE + 1.0f -
                             sqrtf((2.0f * NTILE + 1.0f) * (2.0f * NTILE + 1.0f)
                                   - 8.0f * ff)) * 0.5f);
    while ((by + 1) * (2 * NTILE - by) / 2 <= tid_lin) by++;
    while (by * (2 * NTILE - by + 1) / 2 > tid_lin) by--;
    int bx = by + (tid_lin - by * (2 * NTILE - by + 1) / 2);

    __shared__ __align__(16) float4 sjd[JT][3];   // compute stage; reused as
                                                  // 256x8 word staging buffer

    int t = threadIdx.x;
    int jbase = bx * JT;
    int ibase = by * JT;
    const float4* xv = (const float4*)X;

    {
        float4 a = xv[(jbase + t) * 2 + 0];
        float4 b = xv[(jbase + t) * 2 + 1];
        sjd[t][0] = a;
        sjd[t][1] = b;
        sjd[t][2] = make_float4(norm8(a, b), 0.f, 0.f, 0.f);
    }
    __syncthreads();

    int wid = t >> 5, lane = t & 31;
    int i0 = ibase + lane;                    // rows i0 + 32r, r = 0..7

    ull rp[4][8], sid[4];
#pragma unroll
    for (int p = 0; p < 4; p++) {
        int ra = i0 + 32 * (2 * p), rb = i0 + 32 * (2 * p + 1);
        float4 a0 = xv[ra * 2 + 0], b0 = xv[ra * 2 + 1];
        float4 a1 = xv[rb * 2 + 0], b1 = xv[rb * 2 + 1];
        sid[p] = pack2(norm8(a0, b0), norm8(a1, b1));
        rp[p][0] = pack2(a0.x, a1.x); rp[p][1] = pack2(a0.y, a1.y);
        rp[p][2] = pack2(a0.z, a1.z); rp[p][3] = pack2(a0.w, a1.w);
        rp[p][4] = pack2(b0.x, b1.x); rp[p][5] = pack2(b0.y, b1.y);
        rp[p][6] = pack2(b0.z, b1.z); rp[p][7] = pack2(b0.w, b1.w);
    }
    ull neg2 = pack2(-2.0f, -2.0f);

    int kb = wid * 32;
    unsigned bits[8] = {0, 0, 0, 0, 0, 0, 0, 0};
#pragma unroll 4
    for (int k = 0; k < 32; k++) {
        float4 c = sjd[kb + k][0];
        float4 d = sjd[kb + k][1];
        float n  = sjd[kb + k][2].x;
        ull q0 = pack2(c.x, c.x), q1 = pack2(c.y, c.y);
        ull q2 = pack2(c.z, c.z), q3 = pack2(c.w, c.w);
        ull q4 = pack2(d.x, d.x), q5 = pack2(d.y, d.y);
        ull q6 = pack2(d.z, d.z), q7 = pack2(d.w, d.w);
        ull sq = pack2(n, n);
        unsigned kbit = 1u << k;
#pragma unroll
        for (int p = 0; p < 4; p++) {
            ull acc = mul2(rp[p][0], q0);
            acc = fma2(rp[p][1], q1, acc);
            acc = fma2(rp[p][2], q2, acc);
            acc = fma2(rp[p][3], q3, acc);
            acc = fma2(rp[p][4], q4, acc);
            acc = fma2(rp[p][5], q5, acc);
            acc = fma2(rp[p][6], q6, acc);
            acc = fma2(rp[p][7], q7, acc);
            ull t2 = fma2(acc, neg2, add2(sq, sid[p]));   // (si+sj) - 2*dot
            float lo, hi;
            unpack2(t2, lo, hi);
            if (lo <= EPS2) bits[2 * p]     |= kbit;
            if (hi <= EPS2) bits[2 * p + 1] |= kbit;
        }
    }

    // ---- mirrored tile (lane holds all 8 word-cols of row jbase+kb+lane) ----
    if (bx != by) {
        unsigned tw[8];
#pragma unroll
        for (int r = 0; r < 8; r++)
            tw[r] = bit_transpose32(bits[r], lane);
        int jrow = jbase + kb + lane;
        uint4* dst = (uint4*)&g_adj[jrow * DW + by * 8];
        dst[0] = make_uint4(tw[0], tw[1], tw[2], tw[3]);
        dst[1] = make_uint4(tw[4], tw[5], tw[6], tw[7]);
        int s = __popc(tw[0]) + __popc(tw[1]) + __popc(tw[2]) + __popc(tw[3])
              + __popc(tw[4]) + __popc(tw[5]) + __popc(tw[6]) + __popc(tw[7]);
        g_partial[jrow * NTILE + by] = s;
    }

    // ---- normal tile via smem staging (reuse sjd; all reads of it done) ----
    __syncthreads();
    unsigned* sbuf = (unsigned*)sjd;          // 256 rows x 8 words = 8 KB
#pragma unroll
    for (int r = 0; r < 8; r++)
        sbuf[(lane + 32 * r) * 8 + wid] = bits[r];
    __syncthreads();
    {
        const uint4* s4 = (const uint4*)sbuf;
        uint4 a = s4[t * 2 + 0];
        uint4 b = s4[t * 2 + 1];
        uint4* dst = (uint4*)&g_adj[(ibase + t) * DW + bx * 8];
        dst[0] = a;
        dst[1] = b;
        int s = __popc(a.x) + __popc(a.y) + __popc(a.z) + __popc(a.w)
              + __popc(b.x) + __popc(b.y) + __popc(b.z) + __popc(b.w);
        g_partial[(ibase + t) * NTILE + bx] = s;
    }
}

// ---------------- union-find -------------------------------------------------
__device__ __forceinline__ int uf_find(volatile int* p, int x) {
    int px = p[x];
    while (px != x) {
        int g = p[px];
        if (g != px) p[x] = g;   // path halving; benign race
        x = g;
        px = p[x];
    }
    return x;
}

__device__ __forceinline__ void uf_union(int* p, int a, int b) {
    volatile int* vp = p;
    while (true) {
        a = uf_find(vp, a);
        b = uf_find(vp, b);
        if (a == b) return;
        int hi = a > b ? a : b;
        int lo = a > b ? b : a;
        int old = atomicCAS(&p[hi], hi, lo);
        if (old == hi) return;
        a = lo; b = old;
    }
}

__device__ __forceinline__ int uf_find_ro(const volatile int* p, int x) {
    int px;
    while ((px = p[x]) != x) x = px;
    return x;
}

// ---------------- software grid barrier (gen-based) ---------------------------
__device__ __forceinline__ void grid_sync() {
    __threadfence();
    __syncthreads();
    if (threadIdx.x == 0) {
        int gen = g_bar_gen;
        if (atomicAdd(&g_bar_count, 1) == (int)gridDim.x - 1) {
            g_bar_count = 0;
            __threadfence();
            g_bar_gen = gen + 1;
        } else {
            while (g_bar_gen == gen) { }
        }
    }
    __syncthreads();
    __threadfence();
}

// mask chunk words to keep only j > i (chunk c covers words 4c..4c+3)
__device__ __forceinline__ void mask_gt(unsigned ws[4], int c, int i) {
    int iw = i >> 5;
#pragma unroll
    for (int q = 0; q < 4; q++) {
        int w = 4 * c + q;
        if (w < iw) ws[q] = 0;
        else if (w == iw) {
            int r = i & 31;
            ws[q] &= (r == 31) ? 0u : (0xffffffffu << (r + 1));
        }
    }
}

// ---------------- K2: CC pipeline, one persistent kernel ---------------------
__global__ void __launch_bounds__(1024, 1) k_cc(int* __restrict__ labels) {
    __shared__ int wsum[32];
    __shared__ int s_carry;

    int tid  = threadIdx.x;
    int lane = tid & 31;
    int wid  = tid >> 5;                     // warp in block, 0..31
    int wg   = blockIdx.x * 32 + wid;        // global warp, 0..4735
    int gtid = blockIdx.x * 1024 + tid;      // global thread

    // ---- phase A: density from partials + core + corebits + parent init -----
    if (wg < NPTS / 32) {
        int i = wg * 32 + lane;
        const uint4* p4 = (const uint4*)&g_partial[i * NTILE];
        int s = 0;
#pragma unroll
        for (int q = 0; q < NTILE / 4; q++) {
            uint4 v = p4[q];
            s += (int)(v.x + v.y + v.z + v.w);
        }
        int c = (s >= MIN_SAMPLES) ? 1 : 0;
        g_core[i] = c;
        g_parent[i] = i;
        unsigned b = __ballot_sync(0xffffffffu, c != 0);
        if (lane == 0) g_corebits[wg] = b;
    }
    grid_sync();

    // ---- phase B: atomic-free forest init (first smaller core neighbor) -----
    for (int i = wg; i < NPTS; i += CC_WARPS) {
        if (!g_core[i]) continue;
        int iw = i >> 5;
        for (int base = 0; base <= iw; base += 32) {
            int w = base + lane;
            unsigned word = 0;
            if (w <= iw) {
                word = g_adj[i * DW + w] & g_corebits[w];
                if (w == iw) {
                    int r = i & 31;
                    word &= r ? ((1u << r) - 1u) : 0u;   // only j < i
                }
            }
            unsigned nz = __ballot_sync(0xffffffffu, word != 0);
            if (nz) {
                int w0 = __ffs(nz) - 1;
                unsigned v0 = __shfl_sync(0xffffffffu, word, w0);
                if (lane == 0) g_parent[i] = (base + w0) * 32 + __ffs(v0) - 1;
                break;
            }
        }
    }
    grid_sync();

    // ---- phase C: flatten (race-free: no hooks in flight) --------------------
    if (gtid < NPTS && g_core[gtid]) g_parent[gtid] = uf_find_ro(g_parent, gtid);
    grid_sync();

    // ---- phase D: hook — min over j>i neighbors' roots, ONE atomicMin -------
    for (int i = wg; i < NPTS; i += CC_WARPS) {
        if (!g_core[i]) continue;
        int ri = g_parent[i];
        int m = ri;
        int cbase = (i >> 5) >> 2;
        const uint4* row4 = (const uint4*)&g_adj[i * DW];
        const uint4* cb4  = (const uint4*)g_corebits;
        for (int c = cbase + lane; c < DC; c += 32) {
            uint4 v = row4[c];
            uint4 cb = cb4[c];
            unsigned ws[4] = {v.x & cb.x, v.y & cb.y, v.z & cb.z, v.w & cb.w};
            if (c == cbase) mask_gt(ws, c, i);
#pragma unroll
            for (int q = 0; q < 4; q++) {
                unsigned word = ws[q];
                while (word) {
                    int b = __ffs(word) - 1;
                    word &= word - 1;
                    m = min(m, g_parent[(4 * c + q) * 32 + b]);
                }
            }
        }
#pragma unroll
        for (int o = 16; o; o >>= 1) m = min(m, __shfl_down_sync(0xffffffffu, m, o));
        if (lane == 0 && m < ri) atomicMin(&g_parent[ri], m);
    }
    grid_sync();

    // ---- phase E: flatten ----------------------------------------------------
    if (gtid < NPTS && g_core[gtid]) g_parent[gtid] = uf_find_ro(g_parent, gtid);
    grid_sync();

    // ---- phase F: full edge pass j>i (guaranteed closer; nearly all skip) ---
    for (int i = wg; i < NPTS; i += CC_WARPS) {
        if (!g_core[i]) continue;
        int ri = g_parent[i];                 // flat root (phase E)
        int cbase = (i >> 5) >> 2;
        const uint4* row4 = (const uint4*)&g_adj[i * DW];
        const uint4* cb4  = (const uint4*)g_corebits;
        for (int c = cbase + lane; c < DC; c += 32) {
            uint4 v = row4[c];
            uint4 cb = cb4[c];
            unsigned ws[4] = {v.x & cb.x, v.y & cb.y, v.z & cb.z, v.w & cb.w};
            if (c == cbase) mask_gt(ws, c, i);
#pragma unroll
            for (int q = 0; q < 4; q++) {
                unsigned word = ws[q];
                while (word) {
                    int b = __ffs(word) - 1;
                    word &= word - 1;
                    int j = (4 * c + q) * 32 + b;
                    int pj = g_parent[j];
                    if (pj != ri && j != ri) uf_union(g_parent, ri, j);
                }
            }
        }
    }
    grid_sync();

    // ---- phase G: resolve — core final roots + border minima -----------------
    for (int i = wg; i < NPTS; i += CC_WARPS) {
        if (g_core[i]) {
            if (lane == 0) g_lbl[i] = uf_find(g_parent, i);
            continue;
        }
        int m = NPTS;
        const uint4* row4 = (const uint4*)&g_adj[i * DW];
        const uint4* cb4  = (const uint4*)g_corebits;
        for (int c = lane; c < DC; c += 32) {
            uint4 v = row4[c];
            uint4 cb = cb4[c];
            unsigned ws[4] = {v.x & cb.x, v.y & cb.y, v.z & cb.z, v.w & cb.w};
#pragma unroll
            for (int q = 0; q < 4; q++) {
                unsigned word = ws[q];
                while (word) {
                    int b = __ffs(word) - 1;
                    word &= word - 1;
                    m = min(m, uf_find_ro(g_parent, (4 * c + q) * 32 + b));
                }
            }
        }
#pragma unroll
        for (int o = 16; o; o >>= 1) m = min(m, __shfl_down_sync(0xffffffffu, m, o));
        if (lane == 0) {
            g_root[i] = m;     // NPTS = noise
            g_lbl[i] = NPTS;
        }
    }
    grid_sync();

    // ---- phase H: rank scan + final labels (block 0 only) --------------------
    if (blockIdx.x != 0) return;

    if (tid == 0) s_carry = 0;
    __syncthreads();

    for (int c = 0; c < 12; c++) {
        int e = c * 1024 + tid;
        int r = g_lbl[e];
        int v = (r == e) ? 1 : 0;               // is_root
        unsigned bal = __ballot_sync(0xffffffffu, v);
        int pre = __popc(bal & (0xffffffffu >> (31 - lane)));
        if (lane == 31) wsum[wid] = pre;
        __syncthreads();
        if (wid == 0) {
            int x = wsum[lane];
#pragma unroll
            for (int o = 1; o < 32; o <<= 1) {
                int y = __shfl_up_sync(0xffffffffu, x, o);
                if (lane >= o) x += y;
            }
            wsum[lane] = x;
        }
        __syncthreads();
        int base = s_carry + ((wid > 0) ? wsum[wid - 1] : 0);
        g_rank[e] = base + pre - 1;
        __syncthreads();
        if (tid == 0) s_carry += wsum[31];
        __syncthreads();
    }

    for (int c = 0; c < 12; c++) {
        int e = c * 1024 + tid;
        int r = g_lbl[e];
        if (r >= NPTS) r = g_root[e];           // border/noise
        labels[e] = (r < NPTS) ? g_rank[r] : -1;
    }
}

// ---------------- launcher ----------------------------------------------------
extern "C" void kernel_launch(void* const* d_in, const int* in_sizes, int n_in,
                              void* d_out, int out_size) {
    (void)in_sizes; (void)n_in; (void)out_size;
    const float* X = (const float*)d_in[0];
    int* labels = (int*)d_out;

    k_adj<<<NTRI, 256>>>(X);
    k_cc<<<CC_GRID, 1024>>>(labels);
}

// round 17
// speedup vs baseline: 1.5242x; 1.5242x over previous
#include <cuda_runtime.h>
#include <cstdint>

#define NPTS 12288
#define DW   384           // 32-bit words per adjacency row (12288/32)
#define DC   (DW / 4)      // 96 uint4 chunks per row
#define EPS2 0.25f
#define MIN_SAMPLES 5
#define JT   256           // square tile side in k_adj
#define NTILE 48           // NPTS / JT
#define NTRI  (NTILE * (NTILE + 1) / 2)   // 1176 upper-tri tiles

#define CC_GRID   148
#define CC_WARPS  (CC_GRID * 32)          // 4736 global warps

typedef unsigned long long ull;

// ---------------- device scratch (no dynamic allocation allowed) -------------
__device__ __align__(16) unsigned g_adj[NPTS * DW];    // 18.9 MB adjacency bitmap
__device__ __align__(16) int g_partial[NPTS * NTILE];  // per-(row,tile) popc; every
                                                       // slot written each run
__device__ int      g_parent[NPTS];     // union-find parents
__device__ int      g_core[NPTS];       // core mask
__device__ __align__(16) unsigned g_corebits[DW];      // core mask, bit-packed
__device__ int      g_lbl[NPTS];        // final root per core (NPTS else)
__device__ int      g_root[NPTS];       // border root (non-core rows)
__device__ int      g_rank[NPTS];       // cumsum(is_root)-1

// software grid barrier state (generation-based; survives graph replays)
__device__ volatile int g_bar_gen;
__device__ int          g_bar_count;

// ---------------- f32x2 packed-math helpers (sm_100+) ------------------------
__device__ __forceinline__ ull pack2(float lo, float hi) {
    ull r;
    asm("mov.b64 %0, {%1, %2};" : "=l"(r) : "f"(lo), "f"(hi));
    return r;
}
__device__ __forceinline__ ull mul2(ull a, ull b) {
    ull d;
    asm("mul.rn.f32x2 %0, %1, %2;" : "=l"(d) : "l"(a), "l"(b));
    return d;
}
__device__ __forceinline__ ull fma2(ull a, ull b, ull c) {
    ull d;
    asm("fma.rn.f32x2 %0, %1, %2, %3;" : "=l"(d) : "l"(a), "l"(b), "l"(c));
    return d;
}
__device__ __forceinline__ ull add2(ull a, ull b) {
    ull d;
    asm("add.rn.f32x2 %0, %1, %2;" : "=l"(d) : "l"(a), "l"(b));
    return d;
}
__device__ __forceinline__ void unpack2(ull v, float& lo, float& hi) {
    asm("mov.b64 {%0, %1}, %2;" : "=f"(lo), "=f"(hi) : "l"(v));
}

__device__ __forceinline__ float norm8(float4 a, float4 b) {
    float s = a.x * a.x;
    s = fmaf(a.y, a.y, s);
    s = fmaf(a.z, a.z, s);
    s = fmaf(a.w, a.w, s);
    s = fmaf(b.x, b.x, s);
    s = fmaf(b.y, b.y, s);
    s = fmaf(b.z, b.z, s);
    s = fmaf(b.w, b.w, s);
    return s;
}

// 32x32 bit-matrix transpose within a warp (5 block-swap stages).
__device__ __forceinline__ unsigned bit_transpose32(unsigned x, int lane) {
    const unsigned masks[5] = {0xAAAAAAAAu, 0xCCCCCCCCu, 0xF0F0F0F0u,
                               0xFF00FF00u, 0xFFFF0000u};
#pragma unroll
    for (int si = 0; si < 5; si++) {
        int s = 1 << si;
        unsigned m = masks[si];
        unsigned y = __shfl_xor_sync(0xffffffffu, x, s);
        if (lane & s)
            x = (x & m) | ((y & m) >> s);
        else
            x = (x & ~m) | ((y & ~m) << s);
    }
    return x;
}

// ---------------- K1: adjacency bitmap + per-tile density partials -----------
__global__ void __launch_bounds__(256) k_adj(const float* __restrict__ X) {
    // decode linear tile id -> (by, bx) with bx >= by (row-major upper tri)
    int tid_lin = blockIdx.x;
    float ff = __int2float_rn(tid_lin);
    int by = __float2int_rd((2.0f * NTILE + 1.0f -
                             sqrtf((2.0f * NTILE + 1.0f) * (2.0f * NTILE + 1.0f)
                                   - 8.0f * ff)) * 0.5f);
    while ((by + 1) * (2 * NTILE - by) / 2 <= tid_lin) by++;
    while (by * (2 * NTILE - by + 1) / 2 > tid_lin) by--;
    int bx = by + (tid_lin - by * (2 * NTILE - by + 1) / 2);

    __shared__ __align__(16) float4 sjd[JT][3];   // compute stage; reused as
                                                  // 256x8 word staging buffer

    int t = threadIdx.x;
    int jbase = bx * JT;
    int ibase = by * JT;
    const float4* xv = (const float4*)X;

    {
        float4 a = xv[(jbase + t) * 2 + 0];
        float4 b = xv[(jbase + t) * 2 + 1];
        sjd[t][0] = a;
        sjd[t][1] = b;
        sjd[t][2] = make_float4(norm8(a, b), 0.f, 0.f, 0.f);
    }
    __syncthreads();

    int wid = t >> 5, lane = t & 31;
    int i0 = ibase + lane;                    // rows i0 + 32r, r = 0..7

    ull rp[4][8], sid[4];
#pragma unroll
    for (int p = 0; p < 4; p++) {
        int ra = i0 + 32 * (2 * p), rb = i0 + 32 * (2 * p + 1);
        float4 a0 = xv[ra * 2 + 0], b0 = xv[ra * 2 + 1];
        float4 a1 = xv[rb * 2 + 0], b1 = xv[rb * 2 + 1];
        sid[p] = pack2(norm8(a0, b0), norm8(a1, b1));
        rp[p][0] = pack2(a0.x, a1.x); rp[p][1] = pack2(a0.y, a1.y);
        rp[p][2] = pack2(a0.z, a1.z); rp[p][3] = pack2(a0.w, a1.w);
        rp[p][4] = pack2(b0.x, b1.x); rp[p][5] = pack2(b0.y, b1.y);
        rp[p][6] = pack2(b0.z, b1.z); rp[p][7] = pack2(b0.w, b1.w);
    }
    ull neg2 = pack2(-2.0f, -2.0f);

    int kb = wid * 32;
    unsigned bits[8] = {0, 0, 0, 0, 0, 0, 0, 0};
#pragma unroll 4
    for (int k = 0; k < 32; k++) {
        float4 c = sjd[kb + k][0];
        float4 d = sjd[kb + k][1];
        float n  = sjd[kb + k][2].x;
        ull q0 = pack2(c.x, c.x), q1 = pack2(c.y, c.y);
        ull q2 = pack2(c.z, c.z), q3 = pack2(c.w, c.w);
        ull q4 = pack2(d.x, d.x), q5 = pack2(d.y, d.y);
        ull q6 = pack2(d.z, d.z), q7 = pack2(d.w, d.w);
        ull sq = pack2(n, n);
        unsigned kbit = 1u << k;
#pragma unroll
        for (int p = 0; p < 4; p++) {
            ull acc = mul2(rp[p][0], q0);
            acc = fma2(rp[p][1], q1, acc);
            acc = fma2(rp[p][2], q2, acc);
            acc = fma2(rp[p][3], q3, acc);
            acc = fma2(rp[p][4], q4, acc);
            acc = fma2(rp[p][5], q5, acc);
            acc = fma2(rp[p][6], q6, acc);
            acc = fma2(rp[p][7], q7, acc);
            ull t2 = fma2(acc, neg2, add2(sq, sid[p]));   // (si+sj) - 2*dot
            float lo, hi;
            unpack2(t2, lo, hi);
            if (lo <= EPS2) bits[2 * p]     |= kbit;
            if (hi <= EPS2) bits[2 * p + 1] |= kbit;
        }
    }

    // ---- mirrored tile (lane holds all 8 word-cols of row jbase+kb+lane) ----
    if (bx != by) {
        unsigned tw[8];
#pragma unroll
        for (int r = 0; r < 8; r++)
            tw[r] = bit_transpose32(bits[r], lane);
        int jrow = jbase + kb + lane;
        uint4* dst = (uint4*)&g_adj[jrow * DW + by * 8];
        dst[0] = make_uint4(tw[0], tw[1], tw[2], tw[3]);
        dst[1] = make_uint4(tw[4], tw[5], tw[6], tw[7]);
        int s = __popc(tw[0]) + __popc(tw[1]) + __popc(tw[2]) + __popc(tw[3])
              + __popc(tw[4]) + __popc(tw[5]) + __popc(tw[6]) + __popc(tw[7]);
        g_partial[jrow * NTILE + by] = s;
    }

    // ---- normal tile via smem staging (reuse sjd; all reads of it done) ----
    __syncthreads();
    unsigned* sbuf = (unsigned*)sjd;          // 256 rows x 8 words = 8 KB
#pragma unroll
    for (int r = 0; r < 8; r++)
        sbuf[(lane + 32 * r) * 8 + wid] = bits[r];
    __syncthreads();
    {
        const uint4* s4 = (const uint4*)sbuf;
        uint4 a = s4[t * 2 + 0];
        uint4 b = s4[t * 2 + 1];
        uint4* dst = (uint4*)&g_adj[(ibase + t) * DW + bx * 8];
        dst[0] = a;
        dst[1] = b;
        int s = __popc(a.x) + __popc(a.y) + __popc(a.z) + __popc(a.w)
              + __popc(b.x) + __popc(b.y) + __popc(b.z) + __popc(b.w);
        g_partial[(ibase + t) * NTILE + bx] = s;
    }
}

// ---------------- union-find -------------------------------------------------
__device__ __forceinline__ int uf_find(volatile int* p, int x) {
    int px = p[x];
    while (px != x) {
        int g = p[px];
        if (g != px) p[x] = g;   // path halving; benign race
        x = g;
        px = p[x];
    }
    return x;
}

__device__ __forceinline__ void uf_union(int* p, int a, int b) {
    volatile int* vp = p;
    while (true) {
        a = uf_find(vp, a);
        b = uf_find(vp, b);
        if (a == b) return;
        int hi = a > b ? a : b;
        int lo = a > b ? b : a;
        int old = atomicCAS(&p[hi], hi, lo);
        if (old == hi) return;
        a = lo; b = old;
    }
}

__device__ __forceinline__ int uf_find_ro(const volatile int* p, int x) {
    int px;
    while ((px = p[x]) != x) x = px;
    return x;
}

// ---------------- software grid barrier (gen-based) ---------------------------
__device__ __forceinline__ void grid_sync() {
    __threadfence();
    __syncthreads();
    if (threadIdx.x == 0) {
        int gen = g_bar_gen;
        if (atomicAdd(&g_bar_count, 1) == (int)gridDim.x - 1) {
            g_bar_count = 0;
            __threadfence();
            g_bar_gen = gen + 1;
        } else {
            while (g_bar_gen == gen) { }
        }
    }
    __syncthreads();
    __threadfence();
}

// mask chunk words to keep only j > i (chunk c covers words 4c..4c+3)
__device__ __forceinline__ void mask_gt(unsigned ws[4], int c, int i) {
    int iw = i >> 5;
#pragma unroll
    for (int q = 0; q < 4; q++) {
        int w = 4 * c + q;
        if (w < iw) ws[q] = 0;
        else if (w == iw) {
            int r = i & 31;
            ws[q] &= (r == 31) ? 0u : (0xffffffffu << (r + 1));
        }
    }
}

// ---------------- K2: CC pipeline, one persistent kernel ---------------------
__global__ void __launch_bounds__(1024, 1) k_cc(int* __restrict__ labels) {
    __shared__ int wsum[32];
    __shared__ int s_carry;

    int tid  = threadIdx.x;
    int lane = tid & 31;
    int wid  = tid >> 5;                     // warp in block, 0..31
    int wg   = blockIdx.x * 32 + wid;        // global warp, 0..4735
    int gtid = blockIdx.x * 1024 + tid;      // global thread

    // ---- phase A: density from partials + core + corebits + parent init -----
    if (wg < NPTS / 32) {
        int i = wg * 32 + lane;
        const uint4* p4 = (const uint4*)&g_partial[i * NTILE];
        int s = 0;
#pragma unroll
        for (int q = 0; q < NTILE / 4; q++) {
            uint4 v = p4[q];
            s += (int)(v.x + v.y + v.z + v.w);
        }
        int c = (s >= MIN_SAMPLES) ? 1 : 0;
        g_core[i] = c;
        g_parent[i] = i;
        unsigned b = __ballot_sync(0xffffffffu, c != 0);
        if (lane == 0) g_corebits[wg] = b;
    }
    grid_sync();

    // ---- phase B: atomic-free forest init (first smaller core neighbor) -----
    for (int i = wg; i < NPTS; i += CC_WARPS) {
        if (!g_core[i]) continue;
        int iw = i >> 5;
        for (int base = 0; base <= iw; base += 32) {
            int w = base + lane;
            unsigned word = 0;
            if (w <= iw) {
                word = g_adj[i * DW + w] & g_corebits[w];
                if (w == iw) {
                    int r = i & 31;
                    word &= r ? ((1u << r) - 1u) : 0u;   // only j < i
                }
            }
            unsigned nz = __ballot_sync(0xffffffffu, word != 0);
            if (nz) {
                int w0 = __ffs(nz) - 1;
                unsigned v0 = __shfl_sync(0xffffffffu, word, w0);
                if (lane == 0) g_parent[i] = (base + w0) * 32 + __ffs(v0) - 1;
                break;
            }
        }
    }
    grid_sync();

    // ---- phase C: flatten (race-free: no hooks in flight) --------------------
    if (gtid < NPTS && g_core[gtid]) g_parent[gtid] = uf_find_ro(g_parent, gtid);
    grid_sync();

    // ---- phase D: hook — min over ALL core neighbors' roots, ONE atomicMin --
    for (int i = wg; i < NPTS; i += CC_WARPS) {
        if (!g_core[i]) continue;
        int ri = g_parent[i];
        int m = ri;
        const uint4* row4 = (const uint4*)&g_adj[i * DW];
        const uint4* cb4  = (const uint4*)g_corebits;
        for (int c = lane; c < DC; c += 32) {
            uint4 v = row4[c];
            uint4 cb = cb4[c];
            unsigned ws[4] = {v.x & cb.x, v.y & cb.y, v.z & cb.z, v.w & cb.w};
#pragma unroll
            for (int q = 0; q < 4; q++) {
                unsigned word = ws[q];
                while (word) {
                    int b = __ffs(word) - 1;
                    word &= word - 1;
                    m = min(m, g_parent[(4 * c + q) * 32 + b]);
                }
            }
        }
#pragma unroll
        for (int o = 16; o; o >>= 1) m = min(m, __shfl_down_sync(0xffffffffu, m, o));
        if (lane == 0 && m < ri) atomicMin(&g_parent[ri], m);
    }
    grid_sync();

    // ---- phase E: flatten ----------------------------------------------------
    if (gtid < NPTS && g_core[gtid]) g_parent[gtid] = uf_find_ro(g_parent, gtid);
    grid_sync();

    // ---- phase F: full edge pass j>i, FRESH find (guaranteed closer) --------
    for (int i = wg; i < NPTS; i += CC_WARPS) {
        if (!g_core[i]) continue;
        int ri = uf_find(g_parent, i);
        int cbase = (i >> 5) >> 2;
        const uint4* row4 = (const uint4*)&g_adj[i * DW];
        const uint4* cb4  = (const uint4*)g_corebits;
        for (int c = cbase + lane; c < DC; c += 32) {
            uint4 v = row4[c];
            uint4 cb = cb4[c];
            unsigned ws[4] = {v.x & cb.x, v.y & cb.y, v.z & cb.z, v.w & cb.w};
            if (c == cbase) mask_gt(ws, c, i);
#pragma unroll
            for (int q = 0; q < 4; q++) {
                unsigned word = ws[q];
                while (word) {
                    int b = __ffs(word) - 1;
                    word &= word - 1;
                    int j = (4 * c + q) * 32 + b;
                    int pj = g_parent[j];
                    if (pj != ri && j != ri) uf_union(g_parent, ri, j);
                }
            }
        }
    }
    grid_sync();

    // ---- phase G: resolve — core final roots + border minima -----------------
    for (int i = wg; i < NPTS; i += CC_WARPS) {
        if (g_core[i]) {
            if (lane == 0) g_lbl[i] = uf_find(g_parent, i);
            continue;
        }
        int m = NPTS;
        const uint4* row4 = (const uint4*)&g_adj[i * DW];
        const uint4* cb4  = (const uint4*)g_corebits;
        for (int c = lane; c < DC; c += 32) {
            uint4 v = row4[c];
            uint4 cb = cb4[c];
            unsigned ws[4] = {v.x & cb.x, v.y & cb.y, v.z & cb.z, v.w & cb.w};
#pragma unroll
            for (int q = 0; q < 4; q++) {
                unsigned word = ws[q];
                while (word) {
                    int b = __ffs(word) - 1;
                    word &= word - 1;
                    m = min(m, uf_find_ro(g_parent, (4 * c + q) * 32 + b));
                }
            }
        }
#pragma unroll
        for (int o = 16; o; o >>= 1) m = min(m, __shfl_down_sync(0xffffffffu, m, o));
        if (lane == 0) {
            g_root[i] = m;     // NPTS = noise
            g_lbl[i] = NPTS;
        }
    }
    grid_sync();

    // ---- phase H: rank scan + final labels (block 0 only) --------------------
    if (blockIdx.x != 0) return;

    if (tid == 0) s_carry = 0;
    __syncthreads();

    for (int c = 0; c < 12; c++) {
        int e = c * 1024 + tid;
        int r = g_lbl[e];
        int v = (r == e) ? 1 : 0;               // is_root
        unsigned bal = __ballot_sync(0xffffffffu, v);
        int pre = __popc(bal & (0xffffffffu >> (31 - lane)));
        if (lane == 31) wsum[wid] = pre;
        __syncthreads();
        if (wid == 0) {
            int x = wsum[lane];
#pragma unroll
            for (int o = 1; o < 32; o <<= 1) {
                int y = __shfl_up_sync(0xffffffffu, x, o);
                if (lane >= o) x += y;
            }
            wsum[lane] = x;
        }
        __syncthreads();
        int base = s_carry + ((wid > 0) ? wsum[wid - 1] : 0);
        g_rank[e] = base + pre - 1;
        __syncthreads();
        if (tid == 0) s_carry += wsum[31];
        __syncthreads();
    }

    for (int c = 0; c < 12; c++) {
        int e = c * 1024 + tid;
        int r = g_lbl[e];
        if (r >= NPTS) r = g_root[e];           // border/noise
        labels[e] = (r < NPTS) ? g_rank[r] : -1;
    }
}

// ---------------- launcher ----------------------------------------------------
extern "C" void kernel_launch(void* const* d_in, const int* in_sizes, int n_in,
                              void* d_out, int out_size) {
    (void)in_sizes; (void)n_in; (void)out_size;
    const float* X = (const float*)d_in[0];
    int* labels = (int*)d_out;

    k_adj<<<NTRI, 256>>>(X);
    k_cc<<<CC_GRID, 1024>>>(labels);
}